// round 2
// baseline (speedup 1.0000x reference)
#include <cuda_runtime.h>
#include <cstdint>

// ============================================================
// WeightOnlyInt8Linear: out = input @ weight^T * scales
//   input  [8192, 4096] f32, weight [4096, 4096] int32 (int8 range),
//   scales [4096] f32, out [8192, 4096] f32
//
// Harness compiles for base sm_103 (no 'a'): tcgen05/TMEM unavailable.
// Strategy: Ampere-style tf32 mma.sync.m16n8k8 GEMM (weights exact in
// tf32), cp.async 4-stage pipeline, CTA tile 128x256x32, 512 threads.
// A and W are pre-permuted in global scratch so each mma fragment is a
// single conflict-free LDS.64 (k within each k8 block stored as
// [0,4,1,5,2,6,3,7] so thread t's (k=t, k=t+4) pair is contiguous).
// ============================================================

static constexpr int MDIM = 8192;
static constexpr int NDIM = 4096;
static constexpr int KDIM = 4096;

static constexpr int BM = 128;
static constexpr int BN = 256;
static constexpr int BK = 32;
static constexpr int STAGES = 4;
static constexpr int NKT = KDIM / BK;          // 128 k-tiles

static constexpr int A_STAGE_FLOATS = BM * BK; // 4096  (16 KB)
static constexpr int B_STAGE_FLOATS = BN * BK; // 8192  (32 KB)
static constexpr int STAGE_FLOATS   = A_STAGE_FLOATS + B_STAGE_FLOATS;
static constexpr int SMEM_BYTES     = STAGES * STAGE_FLOATS * 4;  // 196608

// Static device scratch (allocation-free per harness rules)
__device__ float g_wf[(size_t)NDIM * KDIM];   // permuted f32 weight   (64 MB)
__device__ float g_af[(size_t)MDIM * KDIM];   // permuted f32 activ.  (128 MB)

// ---------------- helpers ----------------
__device__ __forceinline__ uint32_t smem_u32(const void* p) {
    uint32_t a;
    asm("{ .reg .u64 t; cvta.to.shared.u64 t, %1; cvt.u32.u64 %0, t; }"
        : "=r"(a) : "l"(p));
    return a;
}

__device__ __forceinline__ void cp_async16(uint32_t dst, const float* src) {
    asm volatile("cp.async.cg.shared.global [%0], [%1], 16;"
                 :: "r"(dst), "l"(src) : "memory");
}

#define CP_COMMIT() asm volatile("cp.async.commit_group;" ::: "memory")
#define CP_WAIT(n)  asm volatile("cp.async.wait_group %0;" :: "n"(n) : "memory")

// d += a * b  (m16n8k8 tf32, fp32 accum)
#define MMA_TF32(d, a, b)                                                    \
    asm volatile("mma.sync.aligned.m16n8k8.row.col.f32.tf32.tf32.f32 "      \
                 "{%0,%1,%2,%3}, {%4,%5,%6,%7}, {%8,%9}, {%0,%1,%2,%3};"    \
                 : "+f"((d)[0]), "+f"((d)[1]), "+f"((d)[2]), "+f"((d)[3])   \
                 : "r"((a)[0]), "r"((a)[1]), "r"((a)[2]), "r"((a)[3]),      \
                   "r"((b)[0]), "r"((b)[1]))

// ---------------- permute passes ----------------
// Within each k8 block, store source k order [0,4,1,5,2,6,3,7] so that the
// mma fragment pair (k=t, k=t+4) is contiguous (one LDS.64).
__global__ void __launch_bounds__(256) permute_w_kernel(const int* __restrict__ w) {
    size_t blk = (size_t)blockIdx.x * 256 + threadIdx.x;   // one k8 block
    const int4* s = reinterpret_cast<const int4*>(w) + blk * 2;
    int4 lo = s[0], hi = s[1];
    float4* d = reinterpret_cast<float4*>(g_wf) + blk * 2;
    d[0] = make_float4((float)lo.x, (float)hi.x, (float)lo.y, (float)hi.y);
    d[1] = make_float4((float)lo.z, (float)hi.z, (float)lo.w, (float)hi.w);
}

__global__ void __launch_bounds__(256) permute_a_kernel(const float* __restrict__ a) {
    size_t blk = (size_t)blockIdx.x * 256 + threadIdx.x;   // one k8 block
    const float4* s = reinterpret_cast<const float4*>(a) + blk * 2;
    float4 lo = s[0], hi = s[1];
    float4* d = reinterpret_cast<float4*>(g_af) + blk * 2;
    d[0] = make_float4(lo.x, hi.x, lo.y, hi.y);
    d[1] = make_float4(lo.z, hi.z, lo.w, hi.w);
}

// ---------------- main GEMM ----------------
__global__ void __launch_bounds__(512, 1) gemm_kernel(
    const float* __restrict__ scales, float* __restrict__ out)
{
    extern __shared__ float smem[];
    const uint32_t s_base = smem_u32(smem);

    const int tid  = threadIdx.x;
    const int lane = tid & 31;
    const int wid  = tid >> 5;
    const int wm   = wid >> 3;        // 0..1  (m warp coord, 64-row slabs)
    const int wn   = wid & 7;         // 0..7  (n warp coord, 32-col slabs)
    const int g    = lane >> 2;       // groupID (0..7)
    const int t    = lane & 3;        // threadID in group (0..3)

    // grouped-M rasterization for L2 reuse
    const int num_n  = NDIM / BN;     // 16
    const int GROUPM = 8;
    int bid = blockIdx.x;
    int grp = bid / (GROUPM * num_n);
    int rem = bid % (GROUPM * num_n);
    const int mt = grp * GROUPM + (rem % GROUPM);
    const int nt = rem / GROUPM;
    const int m0 = mt * BM;
    const int n0 = nt * BN;

    const float* Ag = g_af + (size_t)m0 * KDIM;
    const float* Bg = g_wf + (size_t)n0 * KDIM;

    float acc[4][4][4];
    #pragma unroll
    for (int i = 0; i < 4; i++)
        #pragma unroll
        for (int j = 0; j < 4; j++)
            #pragma unroll
            for (int c = 0; c < 4; c++) acc[i][j][c] = 0.0f;

    // ---- stage loader: smem layout per stage:
    //   A: [b(4)][row(128)][kk(8)]  B: [b(4)][row(256)][kk(8)]
    //   (16B chunk c of a 32-k row: block=c/2, half=c&1 -> contiguous dst)
    #define ISSUE_STAGE(kt_)                                                      \
    do {                                                                          \
        const int _kt = (kt_);                                                    \
        const int _s  = _kt & (STAGES - 1);                                       \
        const uint32_t _sA = s_base + (uint32_t)(_s * STAGE_FLOATS) * 4u;         \
        const uint32_t _sB = _sA + (uint32_t)A_STAGE_FLOATS * 4u;                 \
        const int _k0 = _kt * BK;                                                 \
        _Pragma("unroll")                                                         \
        for (int i = tid; i < BM * 8; i += 512) {                                 \
            int row = i >> 3, c = i & 7;                                          \
            cp_async16(_sA + (uint32_t)(((c >> 1) * (BM * 8)) + row * 8 + (c & 1) * 4) * 4u, \
                       Ag + (size_t)row * KDIM + _k0 + c * 4);                    \
        }                                                                         \
        _Pragma("unroll")                                                         \
        for (int i = tid; i < BN * 8; i += 512) {                                 \
            int row = i >> 3, c = i & 7;                                          \
            cp_async16(_sB + (uint32_t)(((c >> 1) * (BN * 8)) + row * 8 + (c & 1) * 4) * 4u, \
                       Bg + (size_t)row * KDIM + _k0 + c * 4);                    \
        }                                                                         \
    } while (0)

    // prologue: fill STAGES-1 stages
    #pragma unroll
    for (int kt = 0; kt < STAGES - 1; kt++) {
        ISSUE_STAGE(kt);
        CP_COMMIT();
    }

    const int a_row_off = (wm * 64 + g) * 8 + 2 * t;   // float offset, row g slab
    const int b_row_off = (wn * 32 + g) * 8 + 2 * t;

    for (int kt = 0; kt < NKT; kt++) {
        CP_WAIT(STAGES - 2);
        __syncthreads();

        const int kn = kt + STAGES - 1;
        if (kn < NKT) ISSUE_STAGE(kn);
        CP_COMMIT();

        const int s = kt & (STAGES - 1);
        const float* sA = smem + s * STAGE_FLOATS;
        const float* sB = sA + A_STAGE_FLOATS;

        #pragma unroll
        for (int b = 0; b < 4; b++) {
            uint32_t af[4][4];
            #pragma unroll
            for (int i = 0; i < 4; i++) {
                const float* p = sA + b * (BM * 8) + a_row_off + i * (16 * 8);
                float2 lo = *reinterpret_cast<const float2*>(p);          // row g:   k=t, k=t+4
                float2 hi = *reinterpret_cast<const float2*>(p + 8 * 8);  // row g+8
                af[i][0] = __float_as_uint(lo.x);
                af[i][2] = __float_as_uint(lo.y);
                af[i][1] = __float_as_uint(hi.x);
                af[i][3] = __float_as_uint(hi.y);
            }
            uint32_t bf[4][2];
            #pragma unroll
            for (int j = 0; j < 4; j++) {
                const float* p = sB + b * (BN * 8) + b_row_off + j * (8 * 8);
                float2 v = *reinterpret_cast<const float2*>(p);
                bf[j][0] = __float_as_uint(v.x);
                bf[j][1] = __float_as_uint(v.y);
            }
            #pragma unroll
            for (int i = 0; i < 4; i++)
                #pragma unroll
                for (int j = 0; j < 4; j++)
                    MMA_TF32(acc[i][j], af[i], bf[j]);
        }
    }

    // ---- epilogue: scale and store (float2 per mma col-pair) ----
    const int orow0 = m0 + wm * 64;
    const int ocol0 = n0 + wn * 32;
    #pragma unroll
    for (int j = 0; j < 4; j++) {
        const int col = ocol0 + j * 8 + 2 * t;
        const float2 sc = *reinterpret_cast<const float2*>(scales + col);
        #pragma unroll
        for (int i = 0; i < 4; i++) {
            const int row = orow0 + i * 16 + g;
            float2 v0 = { acc[i][j][0] * sc.x, acc[i][j][1] * sc.y };
            float2 v1 = { acc[i][j][2] * sc.x, acc[i][j][3] * sc.y };
            *reinterpret_cast<float2*>(out + (size_t)row * NDIM + col)       = v0;
            *reinterpret_cast<float2*>(out + (size_t)(row + 8) * NDIM + col) = v1;
        }
    }
}

// ---------------- host ----------------
extern "C" void kernel_launch(void* const* d_in, const int* in_sizes, int n_in,
                              void* d_out, int out_size) {
    const float* input  = (const float*)d_in[0];
    const int*   weight = (const int*)d_in[1];
    const float* scales = (const float*)d_in[2];
    float* out = (float*)d_out;

    // 1) permute+convert weight (int32 -> f32, k-interleaved): 8192 blocks
    permute_w_kernel<<<(NDIM * (size_t)KDIM) / 8 / 256, 256>>>(weight);
    // 2) permute activations (k-interleaved): 16384 blocks
    permute_a_kernel<<<(MDIM * (size_t)KDIM) / 8 / 256, 256>>>(input);

    // 3) GEMM
    cudaFuncSetAttribute(gemm_kernel,
                         cudaFuncAttributeMaxDynamicSharedMemorySize, SMEM_BYTES);
    const int grid = (MDIM / BM) * (NDIM / BN);   // 1024 CTAs
    gemm_kernel<<<grid, 512, SMEM_BYTES>>>(scales, out);
}

// round 3
// speedup vs baseline: 1.0350x; 1.0350x over previous
#include <cuda_runtime.h>
#include <cstdint>

// ============================================================
// WeightOnlyInt8Linear: out = input @ weight^T * scales
//   input  [8192, 4096] f32, weight [4096, 4096] int32 (int8 range),
//   scales [4096] f32, out [8192, 4096] f32
//
// Harness targets base sm_103 (no 'a'): tcgen05 unavailable.
// tf32 mma.sync.m16n8k8 GEMM; weights exact in tf32.
// R3 change: 256 threads/CTA (reg budget 256 -> no accumulator
// spills), warp tile 64x64, same CTA tile 128x256x32 + 4-stage
// cp.async pipeline + permuted-k fragment layout (single LDS.64
// per fragment, conflict-free).
// ============================================================

static constexpr int MDIM = 8192;
static constexpr int NDIM = 4096;
static constexpr int KDIM = 4096;

static constexpr int BM = 128;
static constexpr int BN = 256;
static constexpr int BK = 32;
static constexpr int STAGES = 4;
static constexpr int NKT = KDIM / BK;          // 128 k-tiles

static constexpr int A_STAGE_FLOATS = BM * BK; // 4096  (16 KB)
static constexpr int B_STAGE_FLOATS = BN * BK; // 8192  (32 KB)
static constexpr int STAGE_FLOATS   = A_STAGE_FLOATS + B_STAGE_FLOATS;
static constexpr int SMEM_BYTES     = STAGES * STAGE_FLOATS * 4;  // 196608

// Static device scratch (allocation-free per harness rules)
__device__ float g_wf[(size_t)NDIM * KDIM];   // permuted f32 weight   (64 MB)
__device__ float g_af[(size_t)MDIM * KDIM];   // permuted f32 activ.  (128 MB)

// ---------------- helpers ----------------
__device__ __forceinline__ uint32_t smem_u32(const void* p) {
    uint32_t a;
    asm("{ .reg .u64 t; cvta.to.shared.u64 t, %1; cvt.u32.u64 %0, t; }"
        : "=r"(a) : "l"(p));
    return a;
}

__device__ __forceinline__ void cp_async16(uint32_t dst, const float* src) {
    asm volatile("cp.async.cg.shared.global [%0], [%1], 16;"
                 :: "r"(dst), "l"(src) : "memory");
}

#define CP_COMMIT() asm volatile("cp.async.commit_group;" ::: "memory")
#define CP_WAIT(n)  asm volatile("cp.async.wait_group %0;" :: "n"(n) : "memory")

// d += a * b  (m16n8k8 tf32, fp32 accum)
#define MMA_TF32(d, a, b)                                                    \
    asm volatile("mma.sync.aligned.m16n8k8.row.col.f32.tf32.tf32.f32 "      \
                 "{%0,%1,%2,%3}, {%4,%5,%6,%7}, {%8,%9}, {%0,%1,%2,%3};"    \
                 : "+f"((d)[0]), "+f"((d)[1]), "+f"((d)[2]), "+f"((d)[3])   \
                 : "r"((a)[0]), "r"((a)[1]), "r"((a)[2]), "r"((a)[3]),      \
                   "r"((b)[0]), "r"((b)[1]))

// ---------------- permute passes ----------------
// Within each k8 block, store source k order [0,4,1,5,2,6,3,7] so the
// mma fragment pair (k=t, k=t+4) is one contiguous LDS.64.
__global__ void __launch_bounds__(256) permute_w_kernel(const int* __restrict__ w) {
    size_t blk = (size_t)blockIdx.x * 256 + threadIdx.x;   // one k8 block
    const int4* s = reinterpret_cast<const int4*>(w) + blk * 2;
    int4 lo = s[0], hi = s[1];
    float4* d = reinterpret_cast<float4*>(g_wf) + blk * 2;
    d[0] = make_float4((float)lo.x, (float)hi.x, (float)lo.y, (float)hi.y);
    d[1] = make_float4((float)lo.z, (float)hi.z, (float)lo.w, (float)hi.w);
}

__global__ void __launch_bounds__(256) permute_a_kernel(const float* __restrict__ a) {
    size_t blk = (size_t)blockIdx.x * 256 + threadIdx.x;   // one k8 block
    const float4* s = reinterpret_cast<const float4*>(a) + blk * 2;
    float4 lo = s[0], hi = s[1];
    float4* d = reinterpret_cast<float4*>(g_af) + blk * 2;
    d[0] = make_float4(lo.x, hi.x, lo.y, hi.y);
    d[1] = make_float4(lo.z, hi.z, lo.w, hi.w);
}

// ---------------- main GEMM ----------------
__global__ void __launch_bounds__(256, 1) gemm_kernel(
    const float* __restrict__ scales, float* __restrict__ out)
{
    extern __shared__ float smem[];
    const uint32_t s_base = smem_u32(smem);

    const int tid  = threadIdx.x;
    const int lane = tid & 31;
    const int wid  = tid >> 5;        // 0..7
    const int wm   = wid >> 2;        // 0..1  (64-row slab)
    const int wn   = wid & 3;         // 0..3  (64-col slab)
    const int g    = lane >> 2;       // groupID (0..7)
    const int t    = lane & 3;        // threadID in group (0..3)

    // grouped-M rasterization for L2 reuse
    const int num_n  = NDIM / BN;     // 16
    const int GROUPM = 8;
    int bid = blockIdx.x;
    int grp = bid / (GROUPM * num_n);
    int rem = bid % (GROUPM * num_n);
    const int mt = grp * GROUPM + (rem % GROUPM);
    const int nt = rem / GROUPM;
    const int m0 = mt * BM;
    const int n0 = nt * BN;

    const float* Ag = g_af + (size_t)m0 * KDIM;
    const float* Bg = g_wf + (size_t)n0 * KDIM;

    float acc[4][8][4];
    #pragma unroll
    for (int i = 0; i < 4; i++)
        #pragma unroll
        for (int j = 0; j < 8; j++)
            #pragma unroll
            for (int c = 0; c < 4; c++) acc[i][j][c] = 0.0f;

    // ---- stage loader: smem layout per stage:
    //   A: [b(4)][row(128)][kk(8)]  B: [b(4)][row(256)][kk(8)]
    //   (16B chunk c of a 32-k row: block=c/2, half=c&1 -> contiguous dst)
    #define ISSUE_STAGE(kt_)                                                      \
    do {                                                                          \
        const int _kt = (kt_);                                                    \
        const int _s  = _kt & (STAGES - 1);                                       \
        const uint32_t _sA = s_base + (uint32_t)(_s * STAGE_FLOATS) * 4u;         \
        const uint32_t _sB = _sA + (uint32_t)A_STAGE_FLOATS * 4u;                 \
        const int _k0 = _kt * BK;                                                 \
        _Pragma("unroll")                                                         \
        for (int i = tid; i < BM * 8; i += 256) {                                 \
            int row = i >> 3, c = i & 7;                                          \
            cp_async16(_sA + (uint32_t)(((c >> 1) * (BM * 8)) + row * 8 + (c & 1) * 4) * 4u, \
                       Ag + (size_t)row * KDIM + _k0 + c * 4);                    \
        }                                                                         \
        _Pragma("unroll")                                                         \
        for (int i = tid; i < BN * 8; i += 256) {                                 \
            int row = i >> 3, c = i & 7;                                          \
            cp_async16(_sB + (uint32_t)(((c >> 1) * (BN * 8)) + row * 8 + (c & 1) * 4) * 4u, \
                       Bg + (size_t)row * KDIM + _k0 + c * 4);                    \
        }                                                                         \
    } while (0)

    // prologue: fill STAGES-1 stages
    #pragma unroll
    for (int kt = 0; kt < STAGES - 1; kt++) {
        ISSUE_STAGE(kt);
        CP_COMMIT();
    }

    const int a_row_off = (wm * 64 + g) * 8 + 2 * t;   // float offset
    const int b_row_off = (wn * 64 + g) * 8 + 2 * t;

    for (int kt = 0; kt < NKT; kt++) {
        CP_WAIT(STAGES - 2);
        __syncthreads();

        const int kn = kt + STAGES - 1;
        if (kn < NKT) ISSUE_STAGE(kn);
        CP_COMMIT();

        const int s = kt & (STAGES - 1);
        const float* sA = smem + s * STAGE_FLOATS;
        const float* sB = sA + A_STAGE_FLOATS;

        #pragma unroll
        for (int b = 0; b < 4; b++) {
            uint32_t af[4][4];
            #pragma unroll
            for (int i = 0; i < 4; i++) {
                const float* p = sA + b * (BM * 8) + a_row_off + i * (16 * 8);
                float2 lo = *reinterpret_cast<const float2*>(p);          // row g:   k=t, t+4
                float2 hi = *reinterpret_cast<const float2*>(p + 8 * 8);  // row g+8
                af[i][0] = __float_as_uint(lo.x);
                af[i][2] = __float_as_uint(lo.y);
                af[i][1] = __float_as_uint(hi.x);
                af[i][3] = __float_as_uint(hi.y);
            }
            uint32_t bf[8][2];
            #pragma unroll
            for (int j = 0; j < 8; j++) {
                const float* p = sB + b * (BN * 8) + b_row_off + j * (8 * 8);
                float2 v = *reinterpret_cast<const float2*>(p);
                bf[j][0] = __float_as_uint(v.x);
                bf[j][1] = __float_as_uint(v.y);
            }
            #pragma unroll
            for (int i = 0; i < 4; i++)
                #pragma unroll
                for (int j = 0; j < 8; j++)
                    MMA_TF32(acc[i][j], af[i], bf[j]);
        }
    }

    // ---- epilogue: scale and store (float2 per mma col-pair) ----
    const int orow0 = m0 + wm * 64;
    const int ocol0 = n0 + wn * 64;
    #pragma unroll
    for (int j = 0; j < 8; j++) {
        const int col = ocol0 + j * 8 + 2 * t;
        const float2 sc = *reinterpret_cast<const float2*>(scales + col);
        #pragma unroll
        for (int i = 0; i < 4; i++) {
            const int row = orow0 + i * 16 + g;
            float2 v0 = { acc[i][j][0] * sc.x, acc[i][j][1] * sc.y };
            float2 v1 = { acc[i][j][2] * sc.x, acc[i][j][3] * sc.y };
            *reinterpret_cast<float2*>(out + (size_t)row * NDIM + col)       = v0;
            *reinterpret_cast<float2*>(out + (size_t)(row + 8) * NDIM + col) = v1;
        }
    }
}

// ---------------- host ----------------
extern "C" void kernel_launch(void* const* d_in, const int* in_sizes, int n_in,
                              void* d_out, int out_size) {
    const float* input  = (const float*)d_in[0];
    const int*   weight = (const int*)d_in[1];
    const float* scales = (const float*)d_in[2];
    float* out = (float*)d_out;

    // 1) permute+convert weight (int32 -> f32, k-interleaved)
    permute_w_kernel<<<(NDIM * (size_t)KDIM) / 8 / 256, 256>>>(weight);
    // 2) permute activations (k-interleaved)
    permute_a_kernel<<<(MDIM * (size_t)KDIM) / 8 / 256, 256>>>(input);

    // 3) GEMM
    cudaFuncSetAttribute(gemm_kernel,
                         cudaFuncAttributeMaxDynamicSharedMemorySize, SMEM_BYTES);
    const int grid = (MDIM / BM) * (NDIM / BN);   // 1024 CTAs
    gemm_kernel<<<grid, 256, SMEM_BYTES>>>(scales, out);
}